// round 16
// baseline (speedup 1.0000x reference)
#include <cuda_runtime.h>
#include <cuda_bf16.h>
#include <math.h>
#include <stdint.h>

#define HW 16384   // 128*128
#define SDIM 128

// ================= scratch =================
__device__ float g_qkv [8L * 192 * HW];   // [b][192][s]
__device__ float g_qkvT[8L * 192 * HW];   // [b][192][w][h]
__device__ float g_outT[8L * 64 * HW];    // horizontal branch, [b][c][w][h]
__device__ float g_outV[8L * 64 * HW];    // vertical branch,   [b][c][h][w]
__device__ __nv_bfloat16 g_sh[8L * 64 * HW];  // gamma*(h+v) bf16 hi, [b][c][s]
__device__ __nv_bfloat16 g_sl[8L * 64 * HW];  // bf16 lo
__device__ __nv_bfloat16 g_wq_hi[192 * 512], g_wq_lo[192 * 512];
__device__ __nv_bfloat16 g_wo_hi[512 * 64],  g_wo_lo[512 * 64];

// ================= mma helpers =================
__device__ __forceinline__ uint32_t smem_u32(const void* p) {
    uint32_t a;
    asm("{ .reg .u64 t; cvta.to.shared.u64 t, %1; cvt.u32.u64 %0, t; }" : "=r"(a) : "l"(p));
    return a;
}
__device__ __forceinline__ void ldsm4(uint32_t r[4], uint32_t a) {
    asm volatile("ldmatrix.sync.aligned.m8n8.x4.shared.b16 {%0,%1,%2,%3}, [%4];"
        : "=r"(r[0]), "=r"(r[1]), "=r"(r[2]), "=r"(r[3]) : "r"(a));
}
__device__ __forceinline__ void ldsm4t(uint32_t r[4], uint32_t a) {
    asm volatile("ldmatrix.sync.aligned.m8n8.x4.trans.shared.b16 {%0,%1,%2,%3}, [%4];"
        : "=r"(r[0]), "=r"(r[1]), "=r"(r[2]), "=r"(r[3]) : "r"(a));
}
__device__ __forceinline__ void ldsm4_bnk(uint32_t r[4], uint32_t base_bytes, int pitch_bytes) {
    int lane = threadIdx.x & 31;
    int rr = lane & 7, grp = lane >> 3;
    int n = rr + ((grp & 2) ? 8 : 0);
    int k = (grp & 1) ? 8 : 0;
    ldsm4(r, base_bytes + n * pitch_bytes + k * 2);
}
__device__ __forceinline__ void mma16816(float c[4], const uint32_t a[4], const uint32_t b[2]) {
    asm volatile("mma.sync.aligned.m16n8k16.row.col.f32.bf16.bf16.f32 "
        "{%0,%1,%2,%3}, {%4,%5,%6,%7}, {%8,%9}, {%0,%1,%2,%3};"
        : "+f"(c[0]), "+f"(c[1]), "+f"(c[2]), "+f"(c[3])
        : "r"(a[0]), "r"(a[1]), "r"(a[2]), "r"(a[3]), "r"(b[0]), "r"(b[1]));
}
__device__ __forceinline__ void cp16(uint32_t d, const void* s) {
    asm volatile("cp.async.ca.shared.global [%0], [%1], 16;" :: "r"(d), "l"(s));
}
#define CP_COMMIT() asm volatile("cp.async.commit_group;" ::: "memory")
#define CP_WAIT0()  asm volatile("cp.async.wait_group 0;" ::: "memory")

__device__ __forceinline__ uint32_t pk(__nv_bfloat16 a, __nv_bfloat16 b) {
    __nv_bfloat162 t; t.x = a; t.y = b;
    return *reinterpret_cast<uint32_t*>(&t);
}
__device__ __forceinline__ void split4(float4 v, uint2& hi, uint2& lo) {
    __nv_bfloat16 h0 = __float2bfloat16_rn(v.x), h1 = __float2bfloat16_rn(v.y);
    __nv_bfloat16 h2 = __float2bfloat16_rn(v.z), h3 = __float2bfloat16_rn(v.w);
    __nv_bfloat16 l0 = __float2bfloat16_rn(v.x - __bfloat162float(h0));
    __nv_bfloat16 l1 = __float2bfloat16_rn(v.y - __bfloat162float(h1));
    __nv_bfloat16 l2 = __float2bfloat16_rn(v.z - __bfloat162float(h2));
    __nv_bfloat16 l3 = __float2bfloat16_rn(v.w - __bfloat162float(h3));
    hi = make_uint2(pk(h0, h1), pk(h2, h3));
    lo = make_uint2(pk(l0, l1), pk(l2, l3));
}

// ================= merged weight split =================
__global__ __launch_bounds__(256) void split_weights(
    const float* __restrict__ wq, __nv_bfloat16* __restrict__ wqh, __nv_bfloat16* __restrict__ wql,
    const float* __restrict__ wo, __nv_bfloat16* __restrict__ woh, __nv_bfloat16* __restrict__ wol)
{
    const int NQ = 192 * 512, NO = 512 * 64;
    int i = blockIdx.x * 256 + threadIdx.x;
    if (i < NQ) {
        float v = wq[i];
        __nv_bfloat16 h = __float2bfloat16_rn(v);
        wqh[i] = h;
        wql[i] = __float2bfloat16_rn(v - __bfloat162float(h));
    }
    int j = i - NQ;
    if (j >= 0 && j < NO) {
        float v = wo[j];
        __nv_bfloat16 h = __float2bfloat16_rn(v);
        woh[j] = h;
        wol[j] = __float2bfloat16_rn(v - __bfloat162float(h));
    }
}

// ================= GEMM1 (unchanged) =================
#define G1_WH 0
#define G1_WL 7680
#define G1_XH 15360
#define G1_XL 17664
#define G1_BUF 19968
#define G1_SMEM (2 * G1_BUF * 2)

__global__ __launch_bounds__(256, 2) void gemm1_hmma(
    const __nv_bfloat16* __restrict__ Wh, const __nv_bfloat16* __restrict__ Wl,
    const float* __restrict__ x, const float* __restrict__ bias,
    float* __restrict__ outp)
{
    extern __shared__ __nv_bfloat16 sm[];
    const uint32_t sb = smem_u32(sm);
    const int tid = threadIdx.x;
    const int b = blockIdx.y;
    const int s0 = blockIdx.x * 64;
    const float* xb = x + (long)b * 512 * HW;

    const int warp = tid >> 5, lane = tid & 31;
    const int obase = (warp >> 1) * 48;
    const int nbase = (warp & 1) * 32;

    float acc[3][4][4];
#pragma unroll
    for (int m = 0; m < 3; m++)
#pragma unroll
        for (int n = 0; n < 4; n++)
#pragma unroll
            for (int q = 0; q < 4; q++) acc[m][n][q] = 0.f;

    float4 xr[2];

#pragma unroll
    for (int i = 0; i < 3; i++) {
        int fi = tid + i * 256;
        int row = fi >> 2, g = fi & 3;
        cp16(sb + (G1_WH + row * 40 + g * 8) * 2, Wh + row * 512 + g * 8);
        cp16(sb + (G1_WL + row * 40 + g * 8) * 2, Wl + row * 512 + g * 8);
    }
    CP_COMMIT();
#pragma unroll
    for (int i = 0; i < 2; i++) {
        int fi = tid + i * 256;
        int row = fi >> 4, c4 = (fi & 15) * 4;
        xr[i] = *(const float4*)&xb[(long)row * HW + s0 + c4];
    }
#pragma unroll
    for (int i = 0; i < 2; i++) {
        int fi = tid + i * 256;
        int row = fi >> 4, c4 = (fi & 15) * 4;
        uint2 hi, lo; split4(xr[i], hi, lo);
        *(uint2*)&sm[G1_XH + row * 72 + c4] = hi;
        *(uint2*)&sm[G1_XL + row * 72 + c4] = lo;
    }
    CP_WAIT0();
    __syncthreads();

    for (int ch = 0; ch < 16; ch++) {
        const int cur = ch & 1, nxt = cur ^ 1;
        if (ch < 15) {
            const int c0n = (ch + 1) * 32;
#pragma unroll
            for (int i = 0; i < 3; i++) {
                int fi = tid + i * 256;
                int row = fi >> 2, g = fi & 3;
                cp16(sb + (nxt * G1_BUF + G1_WH + row * 40 + g * 8) * 2, Wh + row * 512 + c0n + g * 8);
                cp16(sb + (nxt * G1_BUF + G1_WL + row * 40 + g * 8) * 2, Wl + row * 512 + c0n + g * 8);
            }
            CP_COMMIT();
#pragma unroll
            for (int i = 0; i < 2; i++) {
                int fi = tid + i * 256;
                int row = fi >> 4, c4 = (fi & 15) * 4;
                xr[i] = *(const float4*)&xb[(long)(c0n + row) * HW + s0 + c4];
            }
        }
        const uint32_t wb = sb + (cur * G1_BUF) * 2;
#pragma unroll
        for (int k0 = 0; k0 < 32; k0 += 16) {
            uint32_t Ah[3][4], Al[3][4], B[2][4];
            const int arow = (lane & 15);
            const int acol = k0 + ((lane >> 4) << 3);
#pragma unroll
            for (int m = 0; m < 3; m++) {
                ldsm4(Ah[m], wb + (G1_WH + (obase + m * 16 + arow) * 40 + acol) * 2);
                ldsm4(Al[m], wb + (G1_WL + (obase + m * 16 + arow) * 40 + acol) * 2);
            }
            const int krow = k0 + (lane & 15);
            const int soff = ((lane >> 4) << 3);
#pragma unroll
            for (int j = 0; j < 2; j++)
                ldsm4t(B[j], wb + (G1_XH + krow * 72 + nbase + j * 16 + soff) * 2);
#pragma unroll
            for (int m = 0; m < 3; m++)
#pragma unroll
                for (int j = 0; j < 2; j++) {
                    mma16816(acc[m][2 * j],     Ah[m], &B[j][0]);
                    mma16816(acc[m][2 * j + 1], Ah[m], &B[j][2]);
                }
#pragma unroll
            for (int m = 0; m < 3; m++)
#pragma unroll
                for (int j = 0; j < 2; j++) {
                    mma16816(acc[m][2 * j],     Al[m], &B[j][0]);
                    mma16816(acc[m][2 * j + 1], Al[m], &B[j][2]);
                }
#pragma unroll
            for (int j = 0; j < 2; j++)
                ldsm4t(B[j], wb + (G1_XL + krow * 72 + nbase + j * 16 + soff) * 2);
#pragma unroll
            for (int m = 0; m < 3; m++)
#pragma unroll
                for (int j = 0; j < 2; j++) {
                    mma16816(acc[m][2 * j],     Ah[m], &B[j][0]);
                    mma16816(acc[m][2 * j + 1], Ah[m], &B[j][2]);
                }
        }
        if (ch < 15) {
#pragma unroll
            for (int i = 0; i < 2; i++) {
                int fi = tid + i * 256;
                int row = fi >> 4, c4 = (fi & 15) * 4;
                uint2 hi, lo; split4(xr[i], hi, lo);
                *(uint2*)&sm[nxt * G1_BUF + G1_XH + row * 72 + c4] = hi;
                *(uint2*)&sm[nxt * G1_BUF + G1_XL + row * 72 + c4] = lo;
            }
        }
        CP_WAIT0();
        __syncthreads();
    }

    const int g = lane >> 2, t = lane & 3;
    const long ob = (long)b * 192 * HW;
#pragma unroll
    for (int m = 0; m < 3; m++) {
        int o = obase + m * 16 + g;
        float b0 = bias[o], b1 = bias[o + 8];
#pragma unroll
        for (int n = 0; n < 4; n++) {
            int s = s0 + nbase + n * 8 + 2 * t;
            float2 v0 = make_float2(acc[m][n][0] + b0, acc[m][n][1] + b0);
            float2 v1 = make_float2(acc[m][n][2] + b1, acc[m][n][3] + b1);
            *(float2*)&outp[ob + (long)o * HW + s] = v0;
            *(float2*)&outp[ob + (long)(o + 8) * HW + s] = v1;
        }
    }
}

// ================= GEMM2 (unchanged, pinned 2 CTA) =================
#define G2_AH 0
#define G2_AL 9216
#define G2_SH 18432
#define G2_SL 27136
#define G2_SMEM (35840 * 2)

__global__ __launch_bounds__(256, 2) void gemm2_hmma(
    const __nv_bfloat16* __restrict__ Wh, const __nv_bfloat16* __restrict__ Wl,
    const __nv_bfloat16* __restrict__ Sh, const __nv_bfloat16* __restrict__ Sl,
    const float* __restrict__ bias, const float* __restrict__ resid,
    float* __restrict__ outp)
{
    extern __shared__ __nv_bfloat16 sm[];
    const uint32_t sb = smem_u32(sm);
    const int tid = threadIdx.x;
    const int b = blockIdx.z;
    const int o0 = blockIdx.y * 128;
    const int s0 = blockIdx.x * 128;

#pragma unroll
    for (int i = 0; i < 4; i++) {
        int fi = tid + i * 256;
        int row = fi >> 3, gq = fi & 7;
        *(uint4*)&sm[G2_AH + row * 72 + gq * 8] = *(const uint4*)&Wh[(o0 + row) * 64 + gq * 8];
        *(uint4*)&sm[G2_AL + row * 72 + gq * 8] = *(const uint4*)&Wl[(o0 + row) * 64 + gq * 8];
    }
#pragma unroll
    for (int i = 0; i < 4; i++) {
        int fi = tid + i * 256;
        int row = fi >> 4, gq = fi & 15;
        *(uint4*)&sm[G2_SH + row * 136 + gq * 8] = *(const uint4*)&Sh[((long)b * 64 + row) * HW + s0 + gq * 8];
        *(uint4*)&sm[G2_SL + row * 136 + gq * 8] = *(const uint4*)&Sl[((long)b * 64 + row) * HW + s0 + gq * 8];
    }
    __syncthreads();

    const int warp = tid >> 5, lane = tid & 31;
    const int obase = (warp >> 1) * 32;
    const int sbase = (warp & 1) * 64;

    float acc[2][8][4];
#pragma unroll
    for (int m = 0; m < 2; m++)
#pragma unroll
        for (int n = 0; n < 8; n++)
#pragma unroll
            for (int q = 0; q < 4; q++) acc[m][n][q] = 0.f;

#pragma unroll
    for (int k0 = 0; k0 < 64; k0 += 16) {
        uint32_t Ah[2][4], Al[2][4], B[4][4];
        const int arow = (lane & 15);
        const int acol = k0 + ((lane >> 4) << 3);
#pragma unroll
        for (int m = 0; m < 2; m++) {
            ldsm4(Ah[m], sb + (G2_AH + (obase + m * 16 + arow) * 72 + acol) * 2);
            ldsm4(Al[m], sb + (G2_AL + (obase + m * 16 + arow) * 72 + acol) * 2);
        }
        const int krow = k0 + (lane & 15);
        const int soff = ((lane >> 4) << 3);
#pragma unroll
        for (int j = 0; j < 4; j++)
            ldsm4t(B[j], sb + (G2_SH + krow * 136 + sbase + j * 16 + soff) * 2);
#pragma unroll
        for (int m = 0; m < 2; m++)
#pragma unroll
            for (int j = 0; j < 4; j++) {
                mma16816(acc[m][2 * j],     Ah[m], &B[j][0]);
                mma16816(acc[m][2 * j + 1], Ah[m], &B[j][2]);
            }
#pragma unroll
        for (int m = 0; m < 2; m++)
#pragma unroll
            for (int j = 0; j < 4; j++) {
                mma16816(acc[m][2 * j],     Al[m], &B[j][0]);
                mma16816(acc[m][2 * j + 1], Al[m], &B[j][2]);
            }
#pragma unroll
        for (int j = 0; j < 4; j++)
            ldsm4t(B[j], sb + (G2_SL + krow * 136 + sbase + j * 16 + soff) * 2);
#pragma unroll
        for (int m = 0; m < 2; m++)
#pragma unroll
            for (int j = 0; j < 4; j++) {
                mma16816(acc[m][2 * j],     Ah[m], &B[j][0]);
                mma16816(acc[m][2 * j + 1], Ah[m], &B[j][2]);
            }
    }

    const int g = lane >> 2, t = lane & 3;
#pragma unroll
    for (int m = 0; m < 2; m++) {
        int o = o0 + obase + m * 16 + g;
        float b0 = bias[o], b1 = bias[o + 8];
#pragma unroll
        for (int n = 0; n < 8; n++) {
            int s = s0 + sbase + n * 8 + 2 * t;
            long i0 = ((long)b * 512 + o) * HW + s;
            long i1 = ((long)b * 512 + o + 8) * HW + s;
            float2 r0 = *(const float2*)&resid[i0];
            float2 r1 = *(const float2*)&resid[i1];
            float2 v0 = make_float2(acc[m][n][0] + b0 + r0.x, acc[m][n][1] + b0 + r0.y);
            float2 v1 = make_float2(acc[m][n][2] + b1 + r1.x, acc[m][n][3] + b1 + r1.y);
            *(float2*)&outp[i0] = v0;
            *(float2*)&outp[i1] = v1;
        }
    }
}

// ================= 32x32 transpose, float4 both directions =================
__global__ __launch_bounds__(256) void transpose_hw(const float* __restrict__ in,
                                                    float* __restrict__ out)
{
    __shared__ float tile[32][33];
    const long base = (long)blockIdx.z * HW;
    const int bx = blockIdx.x * 32;   // input col tile
    const int by = blockIdx.y * 32;   // input row tile
    const int tid = threadIdx.x;
    const int row = tid >> 3, c4 = (tid & 7) * 4;

    float4 v = *(const float4*)&in[base + (long)(by + row) * SDIM + bx + c4];
    tile[row][c4 + 0] = v.x;
    tile[row][c4 + 1] = v.y;
    tile[row][c4 + 2] = v.z;
    tile[row][c4 + 3] = v.w;
    __syncthreads();

    float4 o;
    o.x = tile[c4 + 0][row];
    o.y = tile[c4 + 1][row];
    o.z = tile[c4 + 2][row];
    o.w = tile[c4 + 3][row];
    *(float4*)&out[base + (long)(bx + row) * SDIM + by + c4] = o;
}

// ================= HMMA attention, both branches, V loads hoisted =================
#define AT_QH 0
#define AT_QL 8704
#define AT_KH 17408
#define AT_KL 26112
#define AT_ES 34816
#define AT_PH 43136
#define AT_PL 47744
#define AT_SMEM (52352 * 2)

__global__ __launch_bounds__(256, 2) void attn_hmma2(const float* __restrict__ qkvT,
                                                     const float* __restrict__ qkvV,
                                                     float* __restrict__ outT,
                                                     float* __restrict__ outV)
{
    extern __shared__ __nv_bfloat16 sm[];
    const uint32_t sb = smem_u32(sm);
    float* Ef = (float*)(sm + AT_ES);

    const int branch = blockIdx.z;
    const float* qkv = branch ? qkvV : qkvT;
    float* outp      = branch ? outV : outT;

    const int b = blockIdx.y;
    const int s = blockIdx.x;
    const int tid = threadIdx.x;
    const int warp = tid >> 5, lane = tid & 31;
    const long base = (long)b * 192 * HW + (long)s * SDIM;

#pragma unroll
    for (int t = 0; t < 8; t++) {
        int fi = tid + t * 256;
        int row = fi >> 5, c4 = (fi & 31) * 4;
        float4 qv = *(const float4*)&qkv[base + (long)row * HW + c4];
        float4 kv = *(const float4*)&qkv[base + (long)(row + 64) * HW + c4];
        uint2 hi, lo;
        split4(qv, hi, lo);
        *(uint2*)&sm[AT_QH + row * 136 + c4] = hi;
        *(uint2*)&sm[AT_QL + row * 136 + c4] = lo;
        split4(kv, hi, lo);
        *(uint2*)&sm[AT_KH + row * 136 + c4] = hi;
        *(uint2*)&sm[AT_KL + row * 136 + c4] = lo;
    }
    __syncthreads();

    float4 vr[8];
    {
        const int mw = warp >> 1;
        const int nb = (warp & 1) * 32;
        float eacc[4][4];
#pragma unroll
        for (int i = 0; i < 4; i++)
#pragma unroll
            for (int q = 0; q < 4; q++) eacc[i][q] = 0.f;

#pragma unroll
        for (int k0 = 0; k0 < 128; k0 += 16) {
            uint32_t Ah[4], Al[4];
            const uint32_t aoff = ((mw * 16 + (lane & 15)) * 136 + k0 + ((lane >> 4) << 3)) * 2;
            ldsm4(Ah, sb + AT_QH * 2 + aoff);
            ldsm4(Al, sb + AT_QL * 2 + aoff);
#pragma unroll
            for (int j = 0; j < 2; j++) {
                uint32_t Bh[4], Bl[4];
                const uint32_t bbase = ((nb + j * 16) * 136 + k0) * 2;
                ldsm4_bnk(Bh, sb + AT_KH * 2 + bbase, 272);
                ldsm4_bnk(Bl, sb + AT_KL * 2 + bbase, 272);
#pragma unroll
                for (int h = 0; h < 2; h++) {
                    mma16816(eacc[j * 2 + h], Ah, &Bh[h * 2]);
                    mma16816(eacc[j * 2 + h], Ah, &Bl[h * 2]);
                    mma16816(eacc[j * 2 + h], Al, &Bh[h * 2]);
                }
            }
        }
#pragma unroll
        for (int t = 0; t < 8; t++) {
            int fi = tid + t * 256;
            int row = fi >> 5, c4 = (fi & 31) * 4;
            vr[t] = *(const float4*)&qkv[base + (long)(row + 128) * HW + c4];
        }
        const int g = lane >> 2, t = lane & 3;
#pragma unroll
        for (int j = 0; j < 2; j++)
#pragma unroll
            for (int h = 0; h < 2; h++) {
                int n = nb + j * 16 + h * 8 + 2 * t;
                int tt = j * 2 + h;
                Ef[(mw * 16 + g) * 65 + n]     = eacc[tt][0];
                Ef[(mw * 16 + g) * 65 + n + 1] = eacc[tt][1];
                Ef[(mw * 16 + g + 8) * 65 + n]     = eacc[tt][2];
                Ef[(mw * 16 + g + 8) * 65 + n + 1] = eacc[tt][3];
            }
    }
    __syncthreads();

#pragma unroll
    for (int t = 0; t < 8; t++) {
        int fi = tid + t * 256;
        int row = fi >> 5, c4 = (fi & 31) * 4;
        uint2 hi, lo; split4(vr[t], hi, lo);
        *(uint2*)&sm[AT_QH + row * 136 + c4] = hi;
        *(uint2*)&sm[AT_QL + row * 136 + c4] = lo;
    }
    {
        const int row = tid >> 2, t4 = tid & 3;
        float* er = &Ef[row * 65 + t4 * 16];
        float e[16];
        float m = -INFINITY;
#pragma unroll
        for (int j = 0; j < 16; j++) { e[j] = er[j]; m = fmaxf(m, e[j]); }
        m = fmaxf(m, __shfl_xor_sync(0xFFFFFFFFu, m, 1));
        m = fmaxf(m, __shfl_xor_sync(0xFFFFFFFFu, m, 2));
        float ssum = 0.f;
#pragma unroll
        for (int j = 0; j < 16; j++) { e[j] = __expf(e[j] - m); ssum += e[j]; }
        ssum += __shfl_xor_sync(0xFFFFFFFFu, ssum, 1);
        ssum += __shfl_xor_sync(0xFFFFFFFFu, ssum, 2);
        float inv = 1.f / ssum;
#pragma unroll
        for (int c = 0; c < 16; c += 4) {
            float4 v = make_float4(e[c] * inv, e[c + 1] * inv, e[c + 2] * inv, e[c + 3] * inv);
            uint2 hi, lo; split4(v, hi, lo);
            *(uint2*)&sm[AT_PH + row * 72 + t4 * 16 + c] = hi;
            *(uint2*)&sm[AT_PL + row * 72 + t4 * 16 + c] = lo;
        }
    }
    __syncthreads();

    {
        const int mw = warp >> 1;
        const int nb = (warp & 1) * 64;
        float acc[8][4];
#pragma unroll
        for (int n = 0; n < 8; n++)
#pragma unroll
            for (int q = 0; q < 4; q++) acc[n][q] = 0.f;

#pragma unroll
        for (int k0 = 0; k0 < 64; k0 += 16) {
            uint32_t Ph[4], Pl[4];
            const uint32_t aoff = ((mw * 16 + (lane & 15)) * 72 + k0 + ((lane >> 4) << 3)) * 2;
            ldsm4(Ph, sb + AT_PH * 2 + aoff);
            ldsm4(Pl, sb + AT_PL * 2 + aoff);
            const int krow = k0 + (lane & 15);
            const int soff = ((lane >> 4) << 3);
#pragma unroll
            for (int j = 0; j < 4; j++) {
                uint32_t Vh[4], Vl[4];
                const uint32_t boff = (krow * 136 + nb + j * 16 + soff) * 2;
                ldsm4t(Vh, sb + AT_QH * 2 + boff);
                ldsm4t(Vl, sb + AT_QL * 2 + boff);
#pragma unroll
                for (int h = 0; h < 2; h++) {
                    mma16816(acc[j * 2 + h], Ph, &Vh[h * 2]);
                    mma16816(acc[j * 2 + h], Ph, &Vl[h * 2]);
                    mma16816(acc[j * 2 + h], Pl, &Vh[h * 2]);
                }
            }
        }
        const int g = lane >> 2, t = lane & 3;
        const long obase = (long)b * 64 * HW + (long)s * SDIM;
#pragma unroll
        for (int n = 0; n < 8; n++) {
            int col = nb + n * 8 + 2 * t;
            int r0 = mw * 16 + g, r1 = r0 + 8;
            *(float2*)&outp[obase + (long)r0 * HW + col] = make_float2(acc[n][0], acc[n][1]);
            *(float2*)&outp[obase + (long)r1 * HW + col] = make_float2(acc[n][2], acc[n][3]);
        }
    }
}

// ================= combine + bf16 split, vectorized stores =================
__global__ __launch_bounds__(256) void combine_split(const float* __restrict__ outV,
                                                     const float* __restrict__ outT,
                                                     const float* __restrict__ gamma,
                                                     __nv_bfloat16* __restrict__ Sh,
                                                     __nv_bfloat16* __restrict__ Sl)
{
    __shared__ float tile[32][33];   // [w][h]
    const long base = (long)blockIdx.z * HW;
    const int bx = blockIdx.x * 32;   // h tile
    const int by = blockIdx.y * 32;   // w tile
    const int tid = threadIdx.x;
    const float g = *gamma;

    // load outT tile: rows = w, cols = h (coalesced float4 over h)
    {
        const int w = tid >> 3, h4 = (tid & 7) * 4;
        float4 v = *(const float4*)&outT[base + (long)(by + w) * SDIM + bx + h4];
        tile[w][h4 + 0] = v.x;
        tile[w][h4 + 1] = v.y;
        tile[w][h4 + 2] = v.z;
        tile[w][h4 + 3] = v.w;
    }
    __syncthreads();

    // output: h = bx + hh, w4 consecutive; read outV float4, write uint2 Sh/Sl
    {
        const int hh = (tid >> 3);        // 0..31
        const int w4 = (tid & 7) * 4;     // 0,4,...,28
        long idx = base + (long)(bx + hh) * SDIM + by + w4;
        float4 v = *(const float4*)&outV[idx];
        float4 r = make_float4(g * (v.x + tile[w4 + 0][hh]),
                               g * (v.y + tile[w4 + 1][hh]),
                               g * (v.z + tile[w4 + 2][hh]),
                               g * (v.w + tile[w4 + 3][hh]));
        uint2 hi, lo; split4(r, hi, lo);
        *(uint2*)&Sh[idx] = hi;
        *(uint2*)&Sl[idx] = lo;
    }
}

// ================= launch (serial) =================
extern "C" void kernel_launch(void* const* d_in, const int* in_sizes, int n_in,
                              void* d_out, int out_size)
{
    const float* x      = (const float*)d_in[0];
    const float* qkv_w  = (const float*)d_in[1];
    const float* qkv_b  = (const float*)d_in[2];
    const float* out_w  = (const float*)d_in[3];
    const float* out_b  = (const float*)d_in[4];
    const float* gamma  = (const float*)d_in[5];
    float* out = (float*)d_out;
    (void)in_sizes; (void)n_in; (void)out_size;

    float *qkvp, *qkvTp, *outTp, *outVp;
    __nv_bfloat16 *wqh, *wql, *woh, *wol, *shp, *slp;
    cudaGetSymbolAddress((void**)&qkvp,  g_qkv);
    cudaGetSymbolAddress((void**)&qkvTp, g_qkvT);
    cudaGetSymbolAddress((void**)&outTp, g_outT);
    cudaGetSymbolAddress((void**)&outVp, g_outV);
    cudaGetSymbolAddress((void**)&wqh, g_wq_hi);
    cudaGetSymbolAddress((void**)&wql, g_wq_lo);
    cudaGetSymbolAddress((void**)&woh, g_wo_hi);
    cudaGetSymbolAddress((void**)&wol, g_wo_lo);
    cudaGetSymbolAddress((void**)&shp, g_sh);
    cudaGetSymbolAddress((void**)&slp, g_sl);

    cudaFuncSetAttribute(attn_hmma2, cudaFuncAttributeMaxDynamicSharedMemorySize, AT_SMEM);
    cudaFuncSetAttribute(gemm1_hmma, cudaFuncAttributeMaxDynamicSharedMemorySize, G1_SMEM);
    cudaFuncSetAttribute(gemm2_hmma, cudaFuncAttributeMaxDynamicSharedMemorySize, G2_SMEM);

    split_weights<<<(192 * 512 + 512 * 64 + 255) / 256, 256>>>(qkv_w, wqh, wql, out_w, woh, wol);
    gemm1_hmma<<<dim3(256, 8), 256, G1_SMEM>>>(wqh, wql, x, qkv_b, qkvp);
    transpose_hw<<<dim3(4, 4, 8 * 192), 256>>>(qkvp, qkvTp);
    attn_hmma2<<<dim3(128, 8, 2), 256, AT_SMEM>>>(qkvTp, qkvp, outTp, outVp);
    combine_split<<<dim3(4, 4, 8 * 64), 256>>>(outVp, outTp, gamma, shp, slp);
    gemm2_hmma<<<dim3(128, 4, 8), 256, G2_SMEM>>>(woh, wol, shp, slp, out_b, x, out);
}

// round 17
// speedup vs baseline: 1.0021x; 1.0021x over previous
#include <cuda_runtime.h>
#include <cuda_bf16.h>
#include <math.h>
#include <stdint.h>

#define HW 16384   // 128*128
#define SDIM 128

// ================= scratch =================
__device__ float g_qkv [8L * 192 * HW];   // [b][192][s]
__device__ float g_qkvT[8L * 192 * HW];   // [b][192][w][h]
__device__ float g_outT[8L * 64 * HW];    // horizontal branch, [b][c][w][h]
__device__ float g_outV[8L * 64 * HW];    // vertical branch,   [b][c][h][w]
__device__ __nv_bfloat16 g_sh[8L * 64 * HW];  // gamma*(h+v) bf16 hi, [b][c][s]
__device__ __nv_bfloat16 g_sl[8L * 64 * HW];  // bf16 lo
__device__ __nv_bfloat16 g_wq_hi[192 * 512], g_wq_lo[192 * 512];
__device__ __nv_bfloat16 g_wo_hi[512 * 64],  g_wo_lo[512 * 64];

// ================= mma helpers =================
__device__ __forceinline__ uint32_t smem_u32(const void* p) {
    uint32_t a;
    asm("{ .reg .u64 t; cvta.to.shared.u64 t, %1; cvt.u32.u64 %0, t; }" : "=r"(a) : "l"(p));
    return a;
}
__device__ __forceinline__ void ldsm4(uint32_t r[4], uint32_t a) {
    asm volatile("ldmatrix.sync.aligned.m8n8.x4.shared.b16 {%0,%1,%2,%3}, [%4];"
        : "=r"(r[0]), "=r"(r[1]), "=r"(r[2]), "=r"(r[3]) : "r"(a));
}
__device__ __forceinline__ void ldsm4t(uint32_t r[4], uint32_t a) {
    asm volatile("ldmatrix.sync.aligned.m8n8.x4.trans.shared.b16 {%0,%1,%2,%3}, [%4];"
        : "=r"(r[0]), "=r"(r[1]), "=r"(r[2]), "=r"(r[3]) : "r"(a));
}
__device__ __forceinline__ void ldsm4_bnk(uint32_t r[4], uint32_t base_bytes, int pitch_bytes) {
    int lane = threadIdx.x & 31;
    int rr = lane & 7, grp = lane >> 3;
    int n = rr + ((grp & 2) ? 8 : 0);
    int k = (grp & 1) ? 8 : 0;
    ldsm4(r, base_bytes + n * pitch_bytes + k * 2);
}
__device__ __forceinline__ void mma16816(float c[4], const uint32_t a[4], const uint32_t b[2]) {
    asm volatile("mma.sync.aligned.m16n8k16.row.col.f32.bf16.bf16.f32 "
        "{%0,%1,%2,%3}, {%4,%5,%6,%7}, {%8,%9}, {%0,%1,%2,%3};"
        : "+f"(c[0]), "+f"(c[1]), "+f"(c[2]), "+f"(c[3])
        : "r"(a[0]), "r"(a[1]), "r"(a[2]), "r"(a[3]), "r"(b[0]), "r"(b[1]));
}
__device__ __forceinline__ void cp16(uint32_t d, const void* s) {
    asm volatile("cp.async.ca.shared.global [%0], [%1], 16;" :: "r"(d), "l"(s));
}
#define CP_COMMIT() asm volatile("cp.async.commit_group;" ::: "memory")
#define CP_WAIT0()  asm volatile("cp.async.wait_group 0;" ::: "memory")

__device__ __forceinline__ uint32_t pk(__nv_bfloat16 a, __nv_bfloat16 b) {
    __nv_bfloat162 t; t.x = a; t.y = b;
    return *reinterpret_cast<uint32_t*>(&t);
}
__device__ __forceinline__ void split4(float4 v, uint2& hi, uint2& lo) {
    __nv_bfloat16 h0 = __float2bfloat16_rn(v.x), h1 = __float2bfloat16_rn(v.y);
    __nv_bfloat16 h2 = __float2bfloat16_rn(v.z), h3 = __float2bfloat16_rn(v.w);
    __nv_bfloat16 l0 = __float2bfloat16_rn(v.x - __bfloat162float(h0));
    __nv_bfloat16 l1 = __float2bfloat16_rn(v.y - __bfloat162float(h1));
    __nv_bfloat16 l2 = __float2bfloat16_rn(v.z - __bfloat162float(h2));
    __nv_bfloat16 l3 = __float2bfloat16_rn(v.w - __bfloat162float(h3));
    hi = make_uint2(pk(h0, h1), pk(h2, h3));
    lo = make_uint2(pk(l0, l1), pk(l2, l3));
}

// ================= merged weight split (float2 per thread) =================
__global__ __launch_bounds__(256) void split_weights(
    const float* __restrict__ wq, __nv_bfloat16* __restrict__ wqh, __nv_bfloat16* __restrict__ wql,
    const float* __restrict__ wo, __nv_bfloat16* __restrict__ woh, __nv_bfloat16* __restrict__ wol)
{
    const int NQ = 192 * 512, NO = 512 * 64;   // both even
    int i = (blockIdx.x * 256 + threadIdx.x) * 2;
    if (i < NQ) {
        float2 v = *(const float2*)&wq[i];
        __nv_bfloat16 h0 = __float2bfloat16_rn(v.x), h1 = __float2bfloat16_rn(v.y);
        *(uint32_t*)&wqh[i] = pk(h0, h1);
        *(uint32_t*)&wql[i] = pk(__float2bfloat16_rn(v.x - __bfloat162float(h0)),
                                 __float2bfloat16_rn(v.y - __bfloat162float(h1)));
    }
    int j = i - NQ;
    if (j >= 0 && j < NO) {
        float2 v = *(const float2*)&wo[j];
        __nv_bfloat16 h0 = __float2bfloat16_rn(v.x), h1 = __float2bfloat16_rn(v.y);
        *(uint32_t*)&woh[j] = pk(h0, h1);
        *(uint32_t*)&wol[j] = pk(__float2bfloat16_rn(v.x - __bfloat162float(h0)),
                                 __float2bfloat16_rn(v.y - __bfloat162float(h1)));
    }
}

// ================= GEMM1 (unchanged) =================
#define G1_WH 0
#define G1_WL 7680
#define G1_XH 15360
#define G1_XL 17664
#define G1_BUF 19968
#define G1_SMEM (2 * G1_BUF * 2)

__global__ __launch_bounds__(256, 2) void gemm1_hmma(
    const __nv_bfloat16* __restrict__ Wh, const __nv_bfloat16* __restrict__ Wl,
    const float* __restrict__ x, const float* __restrict__ bias,
    float* __restrict__ outp)
{
    extern __shared__ __nv_bfloat16 sm[];
    const uint32_t sb = smem_u32(sm);
    const int tid = threadIdx.x;
    const int b = blockIdx.y;
    const int s0 = blockIdx.x * 64;
    const float* xb = x + (long)b * 512 * HW;

    const int warp = tid >> 5, lane = tid & 31;
    const int obase = (warp >> 1) * 48;
    const int nbase = (warp & 1) * 32;

    float acc[3][4][4];
#pragma unroll
    for (int m = 0; m < 3; m++)
#pragma unroll
        for (int n = 0; n < 4; n++)
#pragma unroll
            for (int q = 0; q < 4; q++) acc[m][n][q] = 0.f;

    float4 xr[2];

#pragma unroll
    for (int i = 0; i < 3; i++) {
        int fi = tid + i * 256;
        int row = fi >> 2, g = fi & 3;
        cp16(sb + (G1_WH + row * 40 + g * 8) * 2, Wh + row * 512 + g * 8);
        cp16(sb + (G1_WL + row * 40 + g * 8) * 2, Wl + row * 512 + g * 8);
    }
    CP_COMMIT();
#pragma unroll
    for (int i = 0; i < 2; i++) {
        int fi = tid + i * 256;
        int row = fi >> 4, c4 = (fi & 15) * 4;
        xr[i] = *(const float4*)&xb[(long)row * HW + s0 + c4];
    }
#pragma unroll
    for (int i = 0; i < 2; i++) {
        int fi = tid + i * 256;
        int row = fi >> 4, c4 = (fi & 15) * 4;
        uint2 hi, lo; split4(xr[i], hi, lo);
        *(uint2*)&sm[G1_XH + row * 72 + c4] = hi;
        *(uint2*)&sm[G1_XL + row * 72 + c4] = lo;
    }
    CP_WAIT0();
    __syncthreads();

    for (int ch = 0; ch < 16; ch++) {
        const int cur = ch & 1, nxt = cur ^ 1;
        if (ch < 15) {
            const int c0n = (ch + 1) * 32;
#pragma unroll
            for (int i = 0; i < 3; i++) {
                int fi = tid + i * 256;
                int row = fi >> 2, g = fi & 3;
                cp16(sb + (nxt * G1_BUF + G1_WH + row * 40 + g * 8) * 2, Wh + row * 512 + c0n + g * 8);
                cp16(sb + (nxt * G1_BUF + G1_WL + row * 40 + g * 8) * 2, Wl + row * 512 + c0n + g * 8);
            }
            CP_COMMIT();
#pragma unroll
            for (int i = 0; i < 2; i++) {
                int fi = tid + i * 256;
                int row = fi >> 4, c4 = (fi & 15) * 4;
                xr[i] = *(const float4*)&xb[(long)(c0n + row) * HW + s0 + c4];
            }
        }
        const uint32_t wb = sb + (cur * G1_BUF) * 2;
#pragma unroll
        for (int k0 = 0; k0 < 32; k0 += 16) {
            uint32_t Ah[3][4], Al[3][4], B[2][4];
            const int arow = (lane & 15);
            const int acol = k0 + ((lane >> 4) << 3);
#pragma unroll
            for (int m = 0; m < 3; m++) {
                ldsm4(Ah[m], wb + (G1_WH + (obase + m * 16 + arow) * 40 + acol) * 2);
                ldsm4(Al[m], wb + (G1_WL + (obase + m * 16 + arow) * 40 + acol) * 2);
            }
            const int krow = k0 + (lane & 15);
            const int soff = ((lane >> 4) << 3);
#pragma unroll
            for (int j = 0; j < 2; j++)
                ldsm4t(B[j], wb + (G1_XH + krow * 72 + nbase + j * 16 + soff) * 2);
#pragma unroll
            for (int m = 0; m < 3; m++)
#pragma unroll
                for (int j = 0; j < 2; j++) {
                    mma16816(acc[m][2 * j],     Ah[m], &B[j][0]);
                    mma16816(acc[m][2 * j + 1], Ah[m], &B[j][2]);
                }
#pragma unroll
            for (int m = 0; m < 3; m++)
#pragma unroll
                for (int j = 0; j < 2; j++) {
                    mma16816(acc[m][2 * j],     Al[m], &B[j][0]);
                    mma16816(acc[m][2 * j + 1], Al[m], &B[j][2]);
                }
#pragma unroll
            for (int j = 0; j < 2; j++)
                ldsm4t(B[j], wb + (G1_XL + krow * 72 + nbase + j * 16 + soff) * 2);
#pragma unroll
            for (int m = 0; m < 3; m++)
#pragma unroll
                for (int j = 0; j < 2; j++) {
                    mma16816(acc[m][2 * j],     Ah[m], &B[j][0]);
                    mma16816(acc[m][2 * j + 1], Ah[m], &B[j][2]);
                }
        }
        if (ch < 15) {
#pragma unroll
            for (int i = 0; i < 2; i++) {
                int fi = tid + i * 256;
                int row = fi >> 4, c4 = (fi & 15) * 4;
                uint2 hi, lo; split4(xr[i], hi, lo);
                *(uint2*)&sm[nxt * G1_BUF + G1_XH + row * 72 + c4] = hi;
                *(uint2*)&sm[nxt * G1_BUF + G1_XL + row * 72 + c4] = lo;
            }
        }
        CP_WAIT0();
        __syncthreads();
    }

    const int g = lane >> 2, t = lane & 3;
    const long ob = (long)b * 192 * HW;
#pragma unroll
    for (int m = 0; m < 3; m++) {
        int o = obase + m * 16 + g;
        float b0 = bias[o], b1 = bias[o + 8];
#pragma unroll
        for (int n = 0; n < 4; n++) {
            int s = s0 + nbase + n * 8 + 2 * t;
            float2 v0 = make_float2(acc[m][n][0] + b0, acc[m][n][1] + b0);
            float2 v1 = make_float2(acc[m][n][2] + b1, acc[m][n][3] + b1);
            *(float2*)&outp[ob + (long)o * HW + s] = v0;
            *(float2*)&outp[ob + (long)(o + 8) * HW + s] = v1;
        }
    }
}

// ================= GEMM2 (unchanged, pinned 2 CTA) =================
#define G2_AH 0
#define G2_AL 9216
#define G2_SH 18432
#define G2_SL 27136
#define G2_SMEM (35840 * 2)

__global__ __launch_bounds__(256, 2) void gemm2_hmma(
    const __nv_bfloat16* __restrict__ Wh, const __nv_bfloat16* __restrict__ Wl,
    const __nv_bfloat16* __restrict__ Sh, const __nv_bfloat16* __restrict__ Sl,
    const float* __restrict__ bias, const float* __restrict__ resid,
    float* __restrict__ outp)
{
    extern __shared__ __nv_bfloat16 sm[];
    const uint32_t sb = smem_u32(sm);
    const int tid = threadIdx.x;
    const int b = blockIdx.z;
    const int o0 = blockIdx.y * 128;
    const int s0 = blockIdx.x * 128;

#pragma unroll
    for (int i = 0; i < 4; i++) {
        int fi = tid + i * 256;
        int row = fi >> 3, gq = fi & 7;
        *(uint4*)&sm[G2_AH + row * 72 + gq * 8] = *(const uint4*)&Wh[(o0 + row) * 64 + gq * 8];
        *(uint4*)&sm[G2_AL + row * 72 + gq * 8] = *(const uint4*)&Wl[(o0 + row) * 64 + gq * 8];
    }
#pragma unroll
    for (int i = 0; i < 4; i++) {
        int fi = tid + i * 256;
        int row = fi >> 4, gq = fi & 15;
        *(uint4*)&sm[G2_SH + row * 136 + gq * 8] = *(const uint4*)&Sh[((long)b * 64 + row) * HW + s0 + gq * 8];
        *(uint4*)&sm[G2_SL + row * 136 + gq * 8] = *(const uint4*)&Sl[((long)b * 64 + row) * HW + s0 + gq * 8];
    }
    __syncthreads();

    const int warp = tid >> 5, lane = tid & 31;
    const int obase = (warp >> 1) * 32;
    const int sbase = (warp & 1) * 64;

    float acc[2][8][4];
#pragma unroll
    for (int m = 0; m < 2; m++)
#pragma unroll
        for (int n = 0; n < 8; n++)
#pragma unroll
            for (int q = 0; q < 4; q++) acc[m][n][q] = 0.f;

#pragma unroll
    for (int k0 = 0; k0 < 64; k0 += 16) {
        uint32_t Ah[2][4], Al[2][4], B[4][4];
        const int arow = (lane & 15);
        const int acol = k0 + ((lane >> 4) << 3);
#pragma unroll
        for (int m = 0; m < 2; m++) {
            ldsm4(Ah[m], sb + (G2_AH + (obase + m * 16 + arow) * 72 + acol) * 2);
            ldsm4(Al[m], sb + (G2_AL + (obase + m * 16 + arow) * 72 + acol) * 2);
        }
        const int krow = k0 + (lane & 15);
        const int soff = ((lane >> 4) << 3);
#pragma unroll
        for (int j = 0; j < 4; j++)
            ldsm4t(B[j], sb + (G2_SH + krow * 136 + sbase + j * 16 + soff) * 2);
#pragma unroll
        for (int m = 0; m < 2; m++)
#pragma unroll
            for (int j = 0; j < 4; j++) {
                mma16816(acc[m][2 * j],     Ah[m], &B[j][0]);
                mma16816(acc[m][2 * j + 1], Ah[m], &B[j][2]);
            }
#pragma unroll
        for (int m = 0; m < 2; m++)
#pragma unroll
            for (int j = 0; j < 4; j++) {
                mma16816(acc[m][2 * j],     Al[m], &B[j][0]);
                mma16816(acc[m][2 * j + 1], Al[m], &B[j][2]);
            }
#pragma unroll
        for (int j = 0; j < 4; j++)
            ldsm4t(B[j], sb + (G2_SL + krow * 136 + sbase + j * 16 + soff) * 2);
#pragma unroll
        for (int m = 0; m < 2; m++)
#pragma unroll
            for (int j = 0; j < 4; j++) {
                mma16816(acc[m][2 * j],     Ah[m], &B[j][0]);
                mma16816(acc[m][2 * j + 1], Ah[m], &B[j][2]);
            }
    }

    const int g = lane >> 2, t = lane & 3;
#pragma unroll
    for (int m = 0; m < 2; m++) {
        int o = o0 + obase + m * 16 + g;
        float b0 = bias[o], b1 = bias[o + 8];
#pragma unroll
        for (int n = 0; n < 8; n++) {
            int s = s0 + sbase + n * 8 + 2 * t;
            long i0 = ((long)b * 512 + o) * HW + s;
            long i1 = ((long)b * 512 + o + 8) * HW + s;
            float2 r0 = *(const float2*)&resid[i0];
            float2 r1 = *(const float2*)&resid[i1];
            float2 v0 = make_float2(acc[m][n][0] + b0 + r0.x, acc[m][n][1] + b0 + r0.y);
            float2 v1 = make_float2(acc[m][n][2] + b1 + r1.x, acc[m][n][3] + b1 + r1.y);
            *(float2*)&outp[i0] = v0;
            *(float2*)&outp[i1] = v1;
        }
    }
}

// ================= 32x32 transpose, float4 both directions =================
__global__ __launch_bounds__(256) void transpose_hw(const float* __restrict__ in,
                                                    float* __restrict__ out)
{
    __shared__ float tile[32][33];
    const long base = (long)blockIdx.z * HW;
    const int bx = blockIdx.x * 32;
    const int by = blockIdx.y * 32;
    const int tid = threadIdx.x;
    const int row = tid >> 3, c4 = (tid & 7) * 4;

    float4 v = *(const float4*)&in[base + (long)(by + row) * SDIM + bx + c4];
    tile[row][c4 + 0] = v.x;
    tile[row][c4 + 1] = v.y;
    tile[row][c4 + 2] = v.z;
    tile[row][c4 + 3] = v.w;
    __syncthreads();

    float4 o;
    o.x = tile[c4 + 0][row];
    o.y = tile[c4 + 1][row];
    o.z = tile[c4 + 2][row];
    o.w = tile[c4 + 3][row];
    *(float4*)&out[base + (long)(bx + row) * SDIM + by + c4] = o;
}

// ================= HMMA attention, both branches; Ef pitch 66 + float2 E-writes =================
#define AT_QH 0
#define AT_QL 8704
#define AT_KH 17408
#define AT_KL 26112
#define AT_ES 34816
#define AT_PH 43328            // AT_ES + 64*66*2 bf16-elems (64*66 floats = 8448 f = 16896 elems)
#define AT_PL 47936
#define AT_SMEM (52544 * 2)    // 105088 bytes

__global__ __launch_bounds__(256, 2) void attn_hmma2(const float* __restrict__ qkvT,
                                                     const float* __restrict__ qkvV,
                                                     float* __restrict__ outT,
                                                     float* __restrict__ outV)
{
    extern __shared__ __nv_bfloat16 sm[];
    const uint32_t sb = smem_u32(sm);
    float* Ef = (float*)(sm + AT_ES);   // [64][66] fp32

    const int branch = blockIdx.z;
    const float* qkv = branch ? qkvV : qkvT;
    float* outp      = branch ? outV : outT;

    const int b = blockIdx.y;
    const int s = blockIdx.x;
    const int tid = threadIdx.x;
    const int warp = tid >> 5, lane = tid & 31;
    const long base = (long)b * 192 * HW + (long)s * SDIM;

#pragma unroll
    for (int t = 0; t < 8; t++) {
        int fi = tid + t * 256;
        int row = fi >> 5, c4 = (fi & 31) * 4;
        float4 qv = *(const float4*)&qkv[base + (long)row * HW + c4];
        float4 kv = *(const float4*)&qkv[base + (long)(row + 64) * HW + c4];
        uint2 hi, lo;
        split4(qv, hi, lo);
        *(uint2*)&sm[AT_QH + row * 136 + c4] = hi;
        *(uint2*)&sm[AT_QL + row * 136 + c4] = lo;
        split4(kv, hi, lo);
        *(uint2*)&sm[AT_KH + row * 136 + c4] = hi;
        *(uint2*)&sm[AT_KL + row * 136 + c4] = lo;
    }
    __syncthreads();

    float4 vr[8];
    {
        const int mw = warp >> 1;
        const int nb = (warp & 1) * 32;
        float eacc[4][4];
#pragma unroll
        for (int i = 0; i < 4; i++)
#pragma unroll
            for (int q = 0; q < 4; q++) eacc[i][q] = 0.f;

#pragma unroll
        for (int k0 = 0; k0 < 128; k0 += 16) {
            uint32_t Ah[4], Al[4];
            const uint32_t aoff = ((mw * 16 + (lane & 15)) * 136 + k0 + ((lane >> 4) << 3)) * 2;
            ldsm4(Ah, sb + AT_QH * 2 + aoff);
            ldsm4(Al, sb + AT_QL * 2 + aoff);
#pragma unroll
            for (int j = 0; j < 2; j++) {
                uint32_t Bh[4], Bl[4];
                const uint32_t bbase = ((nb + j * 16) * 136 + k0) * 2;
                ldsm4_bnk(Bh, sb + AT_KH * 2 + bbase, 272);
                ldsm4_bnk(Bl, sb + AT_KL * 2 + bbase, 272);
#pragma unroll
                for (int h = 0; h < 2; h++) {
                    mma16816(eacc[j * 2 + h], Ah, &Bh[h * 2]);
                    mma16816(eacc[j * 2 + h], Ah, &Bl[h * 2]);
                    mma16816(eacc[j * 2 + h], Al, &Bh[h * 2]);
                }
            }
        }
#pragma unroll
        for (int t = 0; t < 8; t++) {
            int fi = tid + t * 256;
            int row = fi >> 5, c4 = (fi & 31) * 4;
            vr[t] = *(const float4*)&qkv[base + (long)(row + 128) * HW + c4];
        }
        const int g = lane >> 2, t = lane & 3;
#pragma unroll
        for (int j = 0; j < 2; j++)
#pragma unroll
            for (int h = 0; h < 2; h++) {
                int n = nb + j * 16 + h * 8 + 2 * t;   // even
                int tt = j * 2 + h;
                *(float2*)&Ef[(mw * 16 + g) * 66 + n]     = make_float2(eacc[tt][0], eacc[tt][1]);
                *(float2*)&Ef[(mw * 16 + g + 8) * 66 + n] = make_float2(eacc[tt][2], eacc[tt][3]);
            }
    }
    __syncthreads();

#pragma unroll
    for (int t = 0; t < 8; t++) {
        int fi = tid + t * 256;
        int row = fi >> 5, c4 = (fi & 31) * 4;
        uint2 hi, lo; split4(vr[t], hi, lo);
        *(uint2*)&sm[AT_QH + row * 136 + c4] = hi;
        *(uint2*)&sm[AT_QL + row * 136 + c4] = lo;
    }
    {
        const int row = tid >> 2, t4 = tid & 3;
        float* er = &Ef[row * 66 + t4 * 16];
        float e[16];
        float m = -INFINITY;
#pragma unroll
        for (int j = 0; j < 16; j++) { e[j] = er[j]; m = fmaxf(m, e[j]); }
        m = fmaxf(m, __shfl_xor_sync(0xFFFFFFFFu, m, 1));
        m = fmaxf(m, __shfl_xor_sync(0xFFFFFFFFu, m, 2));
        float ssum = 0.f;
#pragma unroll
        for (int j = 0; j < 16; j++) { e[j] = __expf(e[j] - m); ssum += e[j]; }
        ssum += __shfl_xor_sync(0xFFFFFFFFu, ssum, 1);
        ssum += __shfl_xor_sync(0xFFFFFFFFu, ssum, 2);
        float inv = 1.f / ssum;
#pragma unroll
        for (int c = 0; c < 16; c += 4) {
            float4 v = make_float4(e[c] * inv, e[c + 1] * inv, e[c + 2] * inv, e[c + 3] * inv);
            uint2 hi, lo; split4(v, hi, lo);
            *(uint2*)&sm[AT_PH + row * 72 + t4 * 16 + c] = hi;
            *(uint2*)&sm[AT_PL + row * 72 + t4 * 16 + c] = lo;
        }
    }
    __syncthreads();

    {
        const int mw = warp >> 1;
        const int nb = (warp & 1) * 64;
        float acc[8][4];
#pragma unroll
        for (int n = 0; n < 8; n++)
#pragma unroll
            for (int q = 0; q < 4; q++) acc[n][q] = 0.f;

#pragma unroll
        for (int k0 = 0; k0 < 64; k0 += 16) {
            uint32_t Ph[4], Pl[4];
            const uint32_t aoff = ((mw * 16 + (lane & 15)) * 72 + k0 + ((lane >> 4) << 3)) * 2;
            ldsm4(Ph, sb + AT_PH * 2 + aoff);
            ldsm4(Pl, sb + AT_PL * 2 + aoff);
            const int krow = k0 + (lane & 15);
            const int soff = ((lane >> 4) << 3);
#pragma unroll
            for (int j = 0; j < 4; j++) {
                uint32_t Vh[4], Vl[4];
                const uint32_t boff = (krow * 136 + nb + j * 16 + soff) * 2;
                ldsm4t(Vh, sb + AT_QH * 2 + boff);
                ldsm4t(Vl, sb + AT_QL * 2 + boff);
#pragma unroll
                for (int h = 0; h < 2; h++) {
                    mma16816(acc[j * 2 + h], Ph, &Vh[h * 2]);
                    mma16816(acc[j * 2 + h], Ph, &Vl[h * 2]);
                    mma16816(acc[j * 2 + h], Pl, &Vh[h * 2]);
                }
            }
        }
        const int g = lane >> 2, t = lane & 3;
        const long obase = (long)b * 64 * HW + (long)s * SDIM;
#pragma unroll
        for (int n = 0; n < 8; n++) {
            int col = nb + n * 8 + 2 * t;
            int r0 = mw * 16 + g, r1 = r0 + 8;
            *(float2*)&outp[obase + (long)r0 * HW + col] = make_float2(acc[n][0], acc[n][1]);
            *(float2*)&outp[obase + (long)r1 * HW + col] = make_float2(acc[n][2], acc[n][3]);
        }
    }
}

// ================= combine + bf16 split, vectorized =================
__global__ __launch_bounds__(256) void combine_split(const float* __restrict__ outV,
                                                     const float* __restrict__ outT,
                                                     const float* __restrict__ gamma,
                                                     __nv_bfloat16* __restrict__ Sh,
                                                     __nv_bfloat16* __restrict__ Sl)
{
    __shared__ float tile[32][33];   // [w][h]
    const long base = (long)blockIdx.z * HW;
    const int bx = blockIdx.x * 32;   // h tile
    const int by = blockIdx.y * 32;   // w tile
    const int tid = threadIdx.x;
    const float g = *gamma;

    {
        const int w = tid >> 3, h4 = (tid & 7) * 4;
        float4 v = *(const float4*)&outT[base + (long)(by + w) * SDIM + bx + h4];
        tile[w][h4 + 0] = v.x;
        tile[w][h4 + 1] = v.y;
        tile[w][h4 + 2] = v.z;
        tile[w][h4 + 3] = v.w;
    }
    __syncthreads();

    {
        const int hh = (tid >> 3);
        const int w4 = (tid & 7) * 4;
        long idx = base + (long)(bx + hh) * SDIM + by + w4;
        float4 v = *(const float4*)&outV[idx];
        float4 r = make_float4(g * (v.x + tile[w4 + 0][hh]),
                               g * (v.y + tile[w4 + 1][hh]),
                               g * (v.z + tile[w4 + 2][hh]),
                               g * (v.w + tile[w4 + 3][hh]));
        uint2 hi, lo; split4(r, hi, lo);
        *(uint2*)&Sh[idx] = hi;
        *(uint2*)&Sl[idx] = lo;
    }
}

// ================= launch (serial) =================
extern "C" void kernel_launch(void* const* d_in, const int* in_sizes, int n_in,
                              void* d_out, int out_size)
{
    const float* x      = (const float*)d_in[0];
    const float* qkv_w  = (const float*)d_in[1];
    const float* qkv_b  = (const float*)d_in[2];
    const float* out_w  = (const float*)d_in[3];
    const float* out_b  = (const float*)d_in[4];
    const float* gamma  = (const float*)d_in[5];
    float* out = (float*)d_out;
    (void)in_sizes; (void)n_in; (void)out_size;

    float *qkvp, *qkvTp, *outTp, *outVp;
    __nv_bfloat16 *wqh, *wql, *woh, *wol, *shp, *slp;
    cudaGetSymbolAddress((void**)&qkvp,  g_qkv);
    cudaGetSymbolAddress((void**)&qkvTp, g_qkvT);
    cudaGetSymbolAddress((void**)&outTp, g_outT);
    cudaGetSymbolAddress((void**)&outVp, g_outV);
    cudaGetSymbolAddress((void**)&wqh, g_wq_hi);
    cudaGetSymbolAddress((void**)&wql, g_wq_lo);
    cudaGetSymbolAddress((void**)&woh, g_wo_hi);
    cudaGetSymbolAddress((void**)&wol, g_wo_lo);
    cudaGetSymbolAddress((void**)&shp, g_sh);
    cudaGetSymbolAddress((void**)&slp, g_sl);

    cudaFuncSetAttribute(attn_hmma2, cudaFuncAttributeMaxDynamicSharedMemorySize, AT_SMEM);
    cudaFuncSetAttribute(gemm1_hmma, cudaFuncAttributeMaxDynamicSharedMemorySize, G1_SMEM);
    cudaFuncSetAttribute(gemm2_hmma, cudaFuncAttributeMaxDynamicSharedMemorySize, G2_SMEM);

    split_weights<<<((192 * 512 + 512 * 64) / 2 + 255) / 256, 256>>>(qkv_w, wqh, wql, out_w, woh, wol);
    gemm1_hmma<<<dim3(256, 8), 256, G1_SMEM>>>(wqh, wql, x, qkv_b, qkvp);
    transpose_hw<<<dim3(4, 4, 8 * 192), 256>>>(qkvp, qkvTp);
    attn_hmma2<<<dim3(128, 8, 2), 256, AT_SMEM>>>(qkvTp, qkvp, outTp, outVp);
    combine_split<<<dim3(4, 4, 8 * 64), 256>>>(outVp, outTp, gamma, shp, slp);
    gemm2_hmma<<<dim3(128, 4, 8), 256, G2_SMEM>>>(woh, wol, shp, slp, out_b, x, out);
}